// round 6
// baseline (speedup 1.0000x reference)
#include <cuda_runtime.h>
#include <cuda_bf16.h>
#include <math.h>
#include <cstdint>

#define N_TOK 16384
#define DMODEL 896
#define KMAX 3584   // [h | alpha*u | ug | h*ug]
#define INV_SQRT_D 0.03340766f   // 1/sqrt(896)

// ---------------- scratch (device globals) ----------------
__device__ float g_logit_part[N_TOK * 8];
__device__ float g_logit[N_TOK];
__device__ __align__(16) __nv_bfloat16 g_Ahi[(size_t)N_TOK * KMAX];
__device__ __align__(16) __nv_bfloat16 g_Alo[(size_t)N_TOK * KMAX];
__device__ __align__(16) __nv_bfloat16 g_Wahi[DMODEL * DMODEL],     g_Walo[DMODEL * DMODEL];
__device__ __align__(16) __nv_bfloat16 g_Wghi[DMODEL * 2 * DMODEL], g_Wglo[DMODEL * 2 * DMODEL];
__device__ __align__(16) __nv_bfloat16 g_Wfhi[DMODEL * 3 * DMODEL], g_Wflo[DMODEL * 3 * DMODEL];

// ---------------- helpers ----------------
static __device__ __forceinline__ uint32_t smem_u32(const void* p) {
    uint32_t a;
    asm("{ .reg .u64 t; cvta.to.shared.u64 t, %1; cvt.u32.u64 %0, t; }" : "=r"(a) : "l"(p));
    return a;
}
static __device__ __forceinline__ void cp16(uint32_t s, const void* g) {
    asm volatile("cp.async.cg.shared.global [%0], [%1], 16;" :: "r"(s), "l"(g));
}
#define CP_COMMIT() asm volatile("cp.async.commit_group;" ::: "memory")
#define CP_WAIT0()  asm volatile("cp.async.wait_group 0;" ::: "memory")

static __device__ __forceinline__ void ldmx4(uint32_t* r, uint32_t addr) {
    asm volatile("ldmatrix.sync.aligned.m8n8.x4.shared.b16 {%0,%1,%2,%3}, [%4];"
        : "=r"(r[0]), "=r"(r[1]), "=r"(r[2]), "=r"(r[3]) : "r"(addr));
}
static __device__ __forceinline__ void mma16816(float* c, const uint32_t* a,
                                                uint32_t b0, uint32_t b1) {
    asm volatile("mma.sync.aligned.m16n8k16.row.col.f32.bf16.bf16.f32 "
        "{%0,%1,%2,%3}, {%4,%5,%6,%7}, {%8,%9}, {%0,%1,%2,%3};"
        : "+f"(c[0]), "+f"(c[1]), "+f"(c[2]), "+f"(c[3])
        : "r"(a[0]), "r"(a[1]), "r"(a[2]), "r"(a[3]), "r"(b0), "r"(b1));
}

static __device__ __forceinline__ void split_store(__nv_bfloat16* hi, __nv_bfloat16* lo,
                                                   size_t idx, float4 v) {
    uint32_t h01, h23, l01, l23;
    asm("cvt.rn.bf16x2.f32 %0, %1, %2;" : "=r"(h01) : "f"(v.y), "f"(v.x));
    asm("cvt.rn.bf16x2.f32 %0, %1, %2;" : "=r"(h23) : "f"(v.w), "f"(v.z));
    float hx = __uint_as_float(h01 << 16), hy = __uint_as_float(h01 & 0xffff0000u);
    float hz = __uint_as_float(h23 << 16), hw = __uint_as_float(h23 & 0xffff0000u);
    asm("cvt.rn.bf16x2.f32 %0, %1, %2;" : "=r"(l01) : "f"(v.y - hy), "f"(v.x - hx));
    asm("cvt.rn.bf16x2.f32 %0, %1, %2;" : "=r"(l23) : "f"(v.w - hw), "f"(v.z - hz));
    *(uint2*)(hi + idx) = make_uint2(h01, h23);
    *(uint2*)(lo + idx) = make_uint2(l01, l23);
}
static __device__ __forceinline__ void split_store2(__nv_bfloat16* hi, __nv_bfloat16* lo,
                                                    size_t idx, float2 v) {
    uint32_t h01, l01;
    asm("cvt.rn.bf16x2.f32 %0, %1, %2;" : "=r"(h01) : "f"(v.y), "f"(v.x));
    float hx = __uint_as_float(h01 << 16);
    float hy = __uint_as_float(h01 & 0xffff0000u);
    asm("cvt.rn.bf16x2.f32 %0, %1, %2;" : "=r"(l01) : "f"(v.y - hy), "f"(v.x - hx));
    *(uint32_t*)(hi + idx) = h01;
    *(uint32_t*)(lo + idx) = l01;
}

// ---------------- conversion kernels ----------------
__global__ void k_convW_all(const float* __restrict__ wa, const float* __restrict__ wg,
                            const float* __restrict__ wf) {
    int i = blockIdx.x * blockDim.x + threadIdx.x;
    const int n1 = DMODEL * DMODEL / 4;
    const int n2 = DMODEL * 2 * DMODEL / 4;
    const int n3 = DMODEL * 3 * DMODEL / 4;
    if (i < n1) {
        split_store(g_Wahi, g_Walo, (size_t)i * 4, ((const float4*)wa)[i]);
    } else if (i < n1 + n2) {
        int j = i - n1;
        split_store(g_Wghi, g_Wglo, (size_t)j * 4, ((const float4*)wg)[j]);
    } else if (i < n1 + n2 + n3) {
        int j = i - n1 - n2;
        split_store(g_Wfhi, g_Wflo, (size_t)j * 4, ((const float4*)wf)[j]);
    }
}

__global__ void k_convA_hu(const float* __restrict__ h, const float* __restrict__ u) {
    int i = blockIdx.x * blockDim.x + threadIdx.x;
    const int half = N_TOK * 224;
    if (i < half) {
        int row = i / 224, c4 = (i % 224) * 4;
        split_store(g_Ahi, g_Alo, (size_t)row * KMAX + c4,
                    *(const float4*)(h + (size_t)row * DMODEL + c4));
    } else if (i < 2 * half) {
        int j = i - half;
        int row = j / 224, c4 = (j % 224) * 4;
        split_store(g_Ahi, g_Alo, (size_t)row * KMAX + DMODEL + c4,
                    *(const float4*)(u + (size_t)row * DMODEL + c4));
    }
}

__global__ void k_alpha(const float* __restrict__ u) {
    const int row = blockIdx.x * 8 + (threadIdx.x >> 5);
    const int l = threadIdx.x & 31;
    float s = (l < 7) ? g_logit_part[(size_t)row * 8 + l] : 0.f;
    s += __shfl_xor_sync(0xffffffffu, s, 1);
    s += __shfl_xor_sync(0xffffffffu, s, 2);
    s += __shfl_xor_sync(0xffffffffu, s, 4);
    s = __shfl_sync(0xffffffffu, s, 0);
    if (l == 0) g_logit[row] = s;
    const float a = 1.f / (1.f + __expf(-s * INV_SQRT_D));
    const float* ur = u + (size_t)row * DMODEL;
    const size_t base = (size_t)row * KMAX + DMODEL;
#pragma unroll
    for (int j = 0; j < 7; j++) {
        const int c4 = (j * 32 + l) * 4;
        float4 v = *(const float4*)(ur + c4);
        v.x *= a; v.y *= a; v.z *= a; v.w *= a;
        split_store(g_Ahi, g_Alo, base + c4, v);
    }
}

// ---------------- bf16x3 HMMA GEMM: 128x128 CTA tile, 4 warps, warp tile 64x64 ----------------
#define ROWB    80
#define TILE_B  (128 * ROWB)     // 10240
#define T_AHI   0
#define T_ALO   TILE_B
#define T_BHI   (2 * TILE_B)
#define T_BLO   (3 * TILE_B)
#define STAGE_B (4 * TILE_B)     // 40960
#define SMEM_BYTES (2 * STAGE_B) // 81920

template <int MODE>
__global__ void __launch_bounds__(128, 2) hgemm(
    const float* __restrict__ hmat, const float* __restrict__ umat,
    const __nv_bfloat16* __restrict__ Whi, const __nv_bfloat16* __restrict__ Wlo,
    const float* __restrict__ bias, float* __restrict__ dst)
{
    constexpr int K = (MODE == 0) ? 896 : (MODE == 1 ? 1792 : 2688);
    constexpr int AOFF = (MODE == 0) ? 896 : 0;
    constexpr int NT = K / 32;
    extern __shared__ __align__(16) char smem[];
    const uint32_t sb = smem_u32(smem);

    const int tid = threadIdx.x, wid = tid >> 5, l = tid & 31;
    const int cb = blockIdx.x, rb = blockIdx.y;
    const int row0 = rb * 128, col0 = cb * 128;

    // ---- loader mapping: each of 128 threads owns one A row and one B row, all 32 k ----
    const __nv_bfloat16* gAh = g_Ahi + (size_t)(row0 + tid) * KMAX + AOFF;
    const __nv_bfloat16* gAl = g_Alo + (size_t)(row0 + tid) * KMAX + AOFF;
    const __nv_bfloat16* gBh = Whi + (size_t)(col0 + tid) * K;
    const __nv_bfloat16* gBl = Wlo + (size_t)(col0 + tid) * K;
    const uint32_t sl = (uint32_t)(tid * ROWB);

    auto issue = [&](int t) {
        const uint32_t so = sb + (uint32_t)(t & 1) * STAGE_B + sl;
        int go = t * 32;
        int ga = go;
        if (MODE == 2 && ga >= DMODEL) ga += DMODEL;  // skip the alpha*u slot
#pragma unroll
        for (int c = 0; c < 4; c++) {
            cp16(so + T_AHI + c * 16, gAh + ga + c * 8);
            cp16(so + T_ALO + c * 16, gAl + ga + c * 8);
            cp16(so + T_BHI + c * 16, gBh + go + c * 8);
            cp16(so + T_BLO + c * 16, gBl + go + c * 8);
        }
        CP_COMMIT();
    };

    // ---- warp tiling: 2 (M) x 2 (N); warp tile 64x64 ----
    const int wM = wid & 1, wN = wid >> 1;
    const int wMr = wM * 64, wNc = wN * 64;
    const int lq = l >> 2, lr = l & 3;

    float acc[4][8][4];
#pragma unroll
    for (int a = 0; a < 4; a++)
#pragma unroll
        for (int b = 0; b < 8; b++)
#pragma unroll
            for (int c = 0; c < 4; c++) acc[a][b][c] = 0.f;

    const uint32_t aLane = (uint32_t)((wMr + (l & 15)) * ROWB);
    const uint32_t bLane = (uint32_t)((wNc + (l & 15)) * ROWB);
    const uint32_t kHalf = (uint32_t)((l >> 4) * 16);

    issue(0);
    for (int t = 0; t < NT; t++) {
        CP_WAIT0();
        __syncthreads();
        if (t + 1 < NT) issue(t + 1);

        const uint32_t st = sb + (uint32_t)(t & 1) * STAGE_B;
#pragma unroll
        for (int s2 = 0; s2 < 2; s2++) {
            const uint32_t kb = (uint32_t)(s2 * 32) + kHalf;
            uint32_t bh[4][4], bl[4][4];
#pragma unroll
            for (int nj = 0; nj < 4; nj++) {
                ldmx4(bh[nj], st + T_BHI + bLane + (uint32_t)(nj * 16 * ROWB) + kb);
                ldmx4(bl[nj], st + T_BLO + bLane + (uint32_t)(nj * 16 * ROWB) + kb);
            }
#pragma unroll
            for (int mi = 0; mi < 4; mi++) {
                uint32_t ah[4], al[4];
                ldmx4(ah, st + T_AHI + aLane + (uint32_t)(mi * 16 * ROWB) + kb);
                ldmx4(al, st + T_ALO + aLane + (uint32_t)(mi * 16 * ROWB) + kb);
#pragma unroll
                for (int nj = 0; nj < 4; nj++) {
                    mma16816(acc[mi][nj * 2 + 0], ah, bh[nj][0], bh[nj][2]);
                    mma16816(acc[mi][nj * 2 + 1], ah, bh[nj][1], bh[nj][3]);
                }
#pragma unroll
                for (int nj = 0; nj < 4; nj++) {
                    mma16816(acc[mi][nj * 2 + 0], ah, bl[nj][0], bl[nj][2]);
                    mma16816(acc[mi][nj * 2 + 1], ah, bl[nj][1], bl[nj][3]);
                }
#pragma unroll
                for (int nj = 0; nj < 4; nj++) {
                    mma16816(acc[mi][nj * 2 + 0], al, bh[nj][0], bh[nj][2]);
                    mma16816(acc[mi][nj * 2 + 1], al, bh[nj][1], bh[nj][3]);
                }
            }
        }
        __syncthreads();
    }

    // ---- epilogues ----
    // lane (mi, n8): rows wMr+mi*16+lq (+8 for rr=1), cols wNc+n8*8+lr*2 (+1)
    if (MODE == 0) {
        __syncthreads();
        float* red = (float*)smem;  // [128][2]
#pragma unroll
        for (int mi = 0; mi < 4; mi++) {
#pragma unroll
            for (int rr = 0; rr < 2; rr++) {
                const int rloc = wMr + mi * 16 + lq + rr * 8;
                const float* hrow = hmat + (size_t)(row0 + rloc) * DMODEL + col0 + wNc;
                float s = 0.f;
#pragma unroll
                for (int n8 = 0; n8 < 8; n8++) {
                    const int cc = n8 * 8 + lr * 2;
                    float2 h2 = *(const float2*)(hrow + cc);
                    float2 bb = *(const float2*)(bias + col0 + wNc + cc);
                    s += h2.x * (acc[mi][n8][rr * 2 + 0] + bb.x)
                       + h2.y * (acc[mi][n8][rr * 2 + 1] + bb.y);
                }
                s += __shfl_xor_sync(0xffffffffu, s, 1);
                s += __shfl_xor_sync(0xffffffffu, s, 2);
                if (lr == 0) red[rloc * 2 + wN] = s;
            }
        }
        __syncthreads();
        g_logit_part[(size_t)(row0 + tid) * 8 + cb] = red[tid * 2] + red[tid * 2 + 1];
    } else if (MODE == 1) {
#pragma unroll
        for (int mi = 0; mi < 4; mi++) {
#pragma unroll
            for (int rr = 0; rr < 2; rr++) {
                const int rg = row0 + wMr + mi * 16 + lq + rr * 8;
                const float al2 = 1.f / (1.f + __expf(-g_logit[rg] * INV_SQRT_D));
                const float* urow = umat + (size_t)rg * DMODEL + col0 + wNc;
                const float* hrow = hmat + (size_t)rg * DMODEL + col0 + wNc;
                const size_t base1 = (size_t)rg * KMAX + 2 * DMODEL + col0 + wNc;  // ug
                const size_t base2 = (size_t)rg * KMAX + 3 * DMODEL + col0 + wNc;  // h*ug
#pragma unroll
                for (int n8 = 0; n8 < 8; n8++) {
                    const int cc = n8 * 8 + lr * 2;
                    float2 bb = *(const float2*)(bias + col0 + wNc + cc);
                    float2 u2 = *(const float2*)(urow + cc);
                    float2 h2 = *(const float2*)(hrow + cc);
                    float z0 = acc[mi][n8][rr * 2 + 0] + bb.x;
                    float z1 = acc[mi][n8][rr * 2 + 1] + bb.y;
                    float2 o;
                    o.x = al2 * u2.x / (1.f + __expf(-z0));
                    o.y = al2 * u2.y / (1.f + __expf(-z1));
                    split_store2(g_Ahi, g_Alo, base1 + cc, o);
                    split_store2(g_Ahi, g_Alo, base2 + cc,
                                 make_float2(o.x * h2.x, o.y * h2.y));
                }
            }
        }
    } else {
#pragma unroll
        for (int mi = 0; mi < 4; mi++) {
#pragma unroll
            for (int rr = 0; rr < 2; rr++) {
                const int rg = row0 + wMr + mi * 16 + lq + rr * 8;
                float* orow = dst + (size_t)rg * DMODEL + col0 + wNc;
#pragma unroll
                for (int n8 = 0; n8 < 8; n8++) {
                    const int cc = n8 * 8 + lr * 2;
                    float2 bb = *(const float2*)(bias + col0 + wNc + cc);
                    float z0 = acc[mi][n8][rr * 2 + 0] + bb.x;
                    float z1 = acc[mi][n8][rr * 2 + 1] + bb.y;
                    float2 o;
                    o.x = 0.5f * z0 * (1.f + erff(z0 * 0.70710678f));
                    o.y = 0.5f * z1 * (1.f + erff(z1 * 0.70710678f));
                    *(float2*)(orow + cc) = o;
                }
            }
        }
    }
}

extern "C" void kernel_launch(void* const* d_in, const int* in_sizes, int n_in,
                              void* d_out, int out_size) {
    const float* h_t   = (const float*)d_in[0];
    const float* u_t   = (const float*)d_in[1];
    const float* W_a_w = (const float*)d_in[4];
    const float* W_a_b = (const float*)d_in[5];
    const float* W_g_w = (const float*)d_in[6];
    const float* W_g_b = (const float*)d_in[7];
    const float* W_f_w = (const float*)d_in[8];
    const float* W_f_b = (const float*)d_in[9];
    float* out = (float*)d_out;

    cudaFuncSetAttribute(hgemm<0>, cudaFuncAttributeMaxDynamicSharedMemorySize, SMEM_BYTES);
    cudaFuncSetAttribute(hgemm<1>, cudaFuncAttributeMaxDynamicSharedMemorySize, SMEM_BYTES);
    cudaFuncSetAttribute(hgemm<2>, cudaFuncAttributeMaxDynamicSharedMemorySize, SMEM_BYTES);

    __nv_bfloat16 *Wahi, *Walo, *Wghi, *Wglo, *Wfhi, *Wflo;
    cudaGetSymbolAddress((void**)&Wahi, g_Wahi);
    cudaGetSymbolAddress((void**)&Walo, g_Walo);
    cudaGetSymbolAddress((void**)&Wghi, g_Wghi);
    cudaGetSymbolAddress((void**)&Wglo, g_Wglo);
    cudaGetSymbolAddress((void**)&Wfhi, g_Wfhi);
    cudaGetSymbolAddress((void**)&Wflo, g_Wflo);

    dim3 grid(DMODEL / 128, N_TOK / 128);  // (7, 128)
    const int nW = (DMODEL * DMODEL * 6 / 4 + 255) / 256;
    const int nA = (N_TOK * 224 * 2 + 255) / 256;

    k_convW_all<<<nW, 256>>>(W_a_w, W_g_w, W_f_w);                       // 1
    k_convA_hu<<<nA, 256>>>(h_t, u_t);                                   // 2
    hgemm<0><<<grid, 128, SMEM_BYTES>>>(h_t, u_t, Wahi, Walo, W_a_b, nullptr);  // 3
    k_alpha<<<N_TOK / 8, 256>>>(u_t);                                    // 4
    hgemm<1><<<grid, 128, SMEM_BYTES>>>(h_t, u_t, Wghi, Wglo, W_g_b, nullptr);  // 5
    hgemm<2><<<grid, 128, SMEM_BYTES>>>(h_t, u_t, Wfhi, Wflo, W_f_b, out);      // 6
}

// round 7
// speedup vs baseline: 1.1806x; 1.1806x over previous
#include <cuda_runtime.h>
#include <cuda_bf16.h>
#include <math.h>
#include <cstdint>

#define N_TOK 16384
#define DMODEL 896
#define KMAX 3584   // [h | alpha*u | ug | h*ug]
#define INV_SQRT_D 0.03340766f   // 1/sqrt(896)

// ---------------- scratch (device globals) ----------------
__device__ float g_logit_part[N_TOK * 8];
__device__ float g_logit[N_TOK];
__device__ int   g_ticket[N_TOK / 128];
__device__ __align__(16) __nv_bfloat16 g_Ahi[(size_t)N_TOK * KMAX];
__device__ __align__(16) __nv_bfloat16 g_Alo[(size_t)N_TOK * KMAX];
__device__ __align__(16) __nv_bfloat16 g_Wahi[DMODEL * DMODEL],     g_Walo[DMODEL * DMODEL];
__device__ __align__(16) __nv_bfloat16 g_Wghi[DMODEL * 2 * DMODEL], g_Wglo[DMODEL * 2 * DMODEL];
__device__ __align__(16) __nv_bfloat16 g_Wfhi[DMODEL * 3 * DMODEL], g_Wflo[DMODEL * 3 * DMODEL];

// ---------------- helpers ----------------
static __device__ __forceinline__ uint32_t smem_u32(const void* p) {
    uint32_t a;
    asm("{ .reg .u64 t; cvta.to.shared.u64 t, %1; cvt.u32.u64 %0, t; }" : "=r"(a) : "l"(p));
    return a;
}
static __device__ __forceinline__ void cp16(uint32_t s, const void* g) {
    asm volatile("cp.async.cg.shared.global [%0], [%1], 16;" :: "r"(s), "l"(g));
}
#define CP_COMMIT() asm volatile("cp.async.commit_group;" ::: "memory")
#define CP_WAIT0()  asm volatile("cp.async.wait_group 0;" ::: "memory")

static __device__ __forceinline__ void ldmx4(uint32_t* r, uint32_t addr) {
    asm volatile("ldmatrix.sync.aligned.m8n8.x4.shared.b16 {%0,%1,%2,%3}, [%4];"
        : "=r"(r[0]), "=r"(r[1]), "=r"(r[2]), "=r"(r[3]) : "r"(addr));
}
static __device__ __forceinline__ void mma16816(float* c, const uint32_t* a,
                                                uint32_t b0, uint32_t b1) {
    asm volatile("mma.sync.aligned.m16n8k16.row.col.f32.bf16.bf16.f32 "
        "{%0,%1,%2,%3}, {%4,%5,%6,%7}, {%8,%9}, {%0,%1,%2,%3};"
        : "+f"(c[0]), "+f"(c[1]), "+f"(c[2]), "+f"(c[3])
        : "r"(a[0]), "r"(a[1]), "r"(a[2]), "r"(a[3]), "r"(b0), "r"(b1));
}

static __device__ __forceinline__ void split_store(__nv_bfloat16* hi, __nv_bfloat16* lo,
                                                   size_t idx, float4 v) {
    uint32_t h01, h23, l01, l23;
    asm("cvt.rn.bf16x2.f32 %0, %1, %2;" : "=r"(h01) : "f"(v.y), "f"(v.x));
    asm("cvt.rn.bf16x2.f32 %0, %1, %2;" : "=r"(h23) : "f"(v.w), "f"(v.z));
    float hx = __uint_as_float(h01 << 16), hy = __uint_as_float(h01 & 0xffff0000u);
    float hz = __uint_as_float(h23 << 16), hw = __uint_as_float(h23 & 0xffff0000u);
    asm("cvt.rn.bf16x2.f32 %0, %1, %2;" : "=r"(l01) : "f"(v.y - hy), "f"(v.x - hx));
    asm("cvt.rn.bf16x2.f32 %0, %1, %2;" : "=r"(l23) : "f"(v.w - hw), "f"(v.z - hz));
    *(uint2*)(hi + idx) = make_uint2(h01, h23);
    *(uint2*)(lo + idx) = make_uint2(l01, l23);
}
static __device__ __forceinline__ void split_store2(__nv_bfloat16* hi, __nv_bfloat16* lo,
                                                    size_t idx, float2 v) {
    uint32_t h01, l01;
    asm("cvt.rn.bf16x2.f32 %0, %1, %2;" : "=r"(h01) : "f"(v.y), "f"(v.x));
    float hx = __uint_as_float(h01 << 16);
    float hy = __uint_as_float(h01 & 0xffff0000u);
    asm("cvt.rn.bf16x2.f32 %0, %1, %2;" : "=r"(l01) : "f"(v.y - hy), "f"(v.x - hx));
    *(uint32_t*)(hi + idx) = h01;
    *(uint32_t*)(lo + idx) = l01;
}

// ---------------- conversion kernels ----------------
__global__ void k_convW_all(const float* __restrict__ wa, const float* __restrict__ wg,
                            const float* __restrict__ wf) {
    int i = blockIdx.x * blockDim.x + threadIdx.x;
    const int n1 = DMODEL * DMODEL / 4;
    const int n2 = DMODEL * 2 * DMODEL / 4;
    const int n3 = DMODEL * 3 * DMODEL / 4;
    if (i < n1) {
        split_store(g_Wahi, g_Walo, (size_t)i * 4, ((const float4*)wa)[i]);
    } else if (i < n1 + n2) {
        int j = i - n1;
        split_store(g_Wghi, g_Wglo, (size_t)j * 4, ((const float4*)wg)[j]);
    } else if (i < n1 + n2 + n3) {
        int j = i - n1 - n2;
        split_store(g_Wfhi, g_Wflo, (size_t)j * 4, ((const float4*)wf)[j]);
    }
}

// h -> A[0:896], u -> A[896:1792]; also resets the per-row-block tickets
__global__ void k_convA_hu(const float* __restrict__ h, const float* __restrict__ u) {
    int i = blockIdx.x * blockDim.x + threadIdx.x;
    if (i < N_TOK / 128) g_ticket[i] = 0;
    const int half = N_TOK * 224;
    if (i < half) {
        int row = i / 224, c4 = (i % 224) * 4;
        split_store(g_Ahi, g_Alo, (size_t)row * KMAX + c4,
                    *(const float4*)(h + (size_t)row * DMODEL + c4));
    } else if (i < 2 * half) {
        int j = i - half;
        int row = j / 224, c4 = (j % 224) * 4;
        split_store(g_Ahi, g_Alo, (size_t)row * KMAX + DMODEL + c4,
                    *(const float4*)(u + (size_t)row * DMODEL + c4));
    }
}

// ---------------- bf16x3 HMMA GEMM (round-3/5 core: 256 thr, 2x4 warps, 64x32) ----------------
#define ROWB    80
#define TILE_B  (128 * ROWB)     // 10240
#define T_AHI   0
#define T_ALO   TILE_B
#define T_BHI   (2 * TILE_B)
#define T_BLO   (3 * TILE_B)
#define STAGE_B (4 * TILE_B)     // 40960
#define SMEM_BYTES (2 * STAGE_B) // 81920

// MODE 0: K=896 (A = u slot). Epi: logit partials + last-CTA alpha fuse
// MODE 1: K=1792 (A=[h|alpha u]). Epi: ug -> A[1792:2688], h*ug -> A[2688:3584]
// MODE 2: K=2688 (A = {[0:896),[1792:3584)}). Epi: dst = gelu_erf(z)
template <int MODE>
__global__ void __launch_bounds__(256, 2) hgemm(
    const float* __restrict__ hmat, const float* __restrict__ umat,
    const __nv_bfloat16* __restrict__ Whi, const __nv_bfloat16* __restrict__ Wlo,
    const float* __restrict__ bias, float* __restrict__ dst)
{
    constexpr int K = (MODE == 0) ? 896 : (MODE == 1 ? 1792 : 2688);
    constexpr int AOFF = (MODE == 0) ? 896 : 0;
    constexpr int NT = K / 32;
    extern __shared__ __align__(16) char smem[];
    const uint32_t sb = smem_u32(smem);

    const int tid = threadIdx.x, wid = tid >> 5, l = tid & 31;
    const int cb = blockIdx.x, rb = blockIdx.y;
    const int row0 = rb * 128, col0 = cb * 128;

    // ---- loader mapping: each thread owns one smem row, 2 of 4 16B chunks ----
    const int lrow = tid >> 1, lc = (tid & 1) * 2;
    const __nv_bfloat16* gAh = g_Ahi + (size_t)(row0 + lrow) * KMAX + AOFF + lc * 8;
    const __nv_bfloat16* gAl = g_Alo + (size_t)(row0 + lrow) * KMAX + AOFF + lc * 8;
    const __nv_bfloat16* gBh = Whi + (size_t)(col0 + lrow) * K + lc * 8;
    const __nv_bfloat16* gBl = Wlo + (size_t)(col0 + lrow) * K + lc * 8;
    const uint32_t sl = (uint32_t)(lrow * ROWB + lc * 16);

    auto issue = [&](int t) {
        const uint32_t so = sb + (uint32_t)(t & 1) * STAGE_B + sl;
        int go = t * 32;
        int ga = go;
        if (MODE == 2 && ga >= DMODEL) ga += DMODEL;  // skip the alpha*u slot
        cp16(so + T_AHI, gAh + ga);      cp16(so + T_AHI + 16, gAh + ga + 8);
        cp16(so + T_ALO, gAl + ga);      cp16(so + T_ALO + 16, gAl + ga + 8);
        cp16(so + T_BHI, gBh + go);      cp16(so + T_BHI + 16, gBh + go + 8);
        cp16(so + T_BLO, gBl + go);      cp16(so + T_BLO + 16, gBl + go + 8);
        CP_COMMIT();
    };

    // ---- warp tiling: 2 (M) x 4 (N); warp tile 64x32 ----
    const int wM = wid & 1, wN = wid >> 1;
    const int wMr = wM * 64, wNc = wN * 32;
    const int lq = l >> 2, lr = l & 3;

    float acc[4][4][4];
#pragma unroll
    for (int a = 0; a < 4; a++)
#pragma unroll
        for (int b = 0; b < 4; b++)
#pragma unroll
            for (int c = 0; c < 4; c++) acc[a][b][c] = 0.f;

    const uint32_t aLane = (uint32_t)((wMr + (l & 15)) * ROWB);
    const uint32_t bLane0 = (uint32_t)((wNc + (l & 15)) * ROWB);
    const uint32_t kHalf = (uint32_t)((l >> 4) * 8) * 2;

    issue(0);
    for (int t = 0; t < NT; t++) {
        CP_WAIT0();
        __syncthreads();
        if (t + 1 < NT) issue(t + 1);

        const uint32_t st = sb + (uint32_t)(t & 1) * STAGE_B;
#pragma unroll
        for (int s2 = 0; s2 < 2; s2++) {
            const uint32_t kb = (uint32_t)(s2 * 32) + kHalf;
            uint32_t bh[2][4], bl[2][4];
#pragma unroll
            for (int nj = 0; nj < 2; nj++) {
                ldmx4(bh[nj], st + T_BHI + bLane0 + (uint32_t)(nj * 16 * ROWB) + kb);
                ldmx4(bl[nj], st + T_BLO + bLane0 + (uint32_t)(nj * 16 * ROWB) + kb);
            }
#pragma unroll
            for (int mi = 0; mi < 4; mi++) {
                uint32_t af[4];
                ldmx4(af, st + T_AHI + aLane + (uint32_t)(mi * 16 * ROWB) + kb);
#pragma unroll
                for (int nj = 0; nj < 2; nj++) {
                    mma16816(acc[mi][nj * 2 + 0], af, bh[nj][0], bh[nj][2]);
                    mma16816(acc[mi][nj * 2 + 1], af, bh[nj][1], bh[nj][3]);
                }
#pragma unroll
                for (int nj = 0; nj < 2; nj++) {
                    mma16816(acc[mi][nj * 2 + 0], af, bl[nj][0], bl[nj][2]);
                    mma16816(acc[mi][nj * 2 + 1], af, bl[nj][1], bl[nj][3]);
                }
                ldmx4(af, st + T_ALO + aLane + (uint32_t)(mi * 16 * ROWB) + kb);
#pragma unroll
                for (int nj = 0; nj < 2; nj++) {
                    mma16816(acc[mi][nj * 2 + 0], af, bh[nj][0], bh[nj][2]);
                    mma16816(acc[mi][nj * 2 + 1], af, bh[nj][1], bh[nj][3]);
                }
            }
        }
        __syncthreads();
    }

    // ---- epilogues ----
    if (MODE == 0) {
        __syncthreads();
        float* red = (float*)smem;  // [128][4]
#pragma unroll
        for (int mi = 0; mi < 4; mi++) {
#pragma unroll
            for (int rr = 0; rr < 2; rr++) {
                const int rloc = wMr + mi * 16 + lq + rr * 8;
                const float* hrow = hmat + (size_t)(row0 + rloc) * DMODEL + col0 + wNc;
                float s = 0.f;
#pragma unroll
                for (int n8 = 0; n8 < 4; n8++) {
                    const int cc = n8 * 8 + lr * 2;
                    float2 h2 = *(const float2*)(hrow + cc);
                    float2 bb = *(const float2*)(bias + col0 + wNc + cc);
                    s += h2.x * (acc[mi][n8][rr * 2 + 0] + bb.x)
                       + h2.y * (acc[mi][n8][rr * 2 + 1] + bb.y);
                }
                s += __shfl_xor_sync(0xffffffffu, s, 1);
                s += __shfl_xor_sync(0xffffffffu, s, 2);
                if (lr == 0) red[rloc * 4 + wN] = s;
            }
        }
        __syncthreads();
        if (tid < 128) {
            float s = red[tid * 4] + red[tid * 4 + 1] + red[tid * 4 + 2] + red[tid * 4 + 3];
            g_logit_part[(size_t)(row0 + tid) * 8 + cb] = s;
        }
        // ---- fused alpha: last CTA of this row-block reduces and writes alpha*u split ----
        __threadfence();
        __syncthreads();
        __shared__ int s_ticket;
        if (tid == 0) s_ticket = atomicAdd(&g_ticket[rb], 1);
        __syncthreads();
        if (s_ticket == 6) {
            __threadfence();  // acquire: see all 7 CTAs' partials
            const int r = tid >> 1;        // 0..127
            const int half = tid & 1;      // 0..1
            const int row = row0 + r;
            float s = 0.f;
#pragma unroll
            for (int b = 0; b < 7; b++) s += g_logit_part[(size_t)row * 8 + b];
            if (half == 0) g_logit[row] = s;
            const float a = 1.f / (1.f + __expf(-s * INV_SQRT_D));
            const float* ur = umat + (size_t)row * DMODEL + half * 448;
            const size_t base = (size_t)row * KMAX + DMODEL + half * 448;
#pragma unroll 4
            for (int j = 0; j < 112; j++) {
                float4 v = *(const float4*)(ur + j * 4);
                v.x *= a; v.y *= a; v.z *= a; v.w *= a;
                split_store(g_Ahi, g_Alo, base + j * 4, v);
            }
        }
    } else if (MODE == 1) {
#pragma unroll
        for (int mi = 0; mi < 4; mi++) {
#pragma unroll
            for (int rr = 0; rr < 2; rr++) {
                const int rg = row0 + wMr + mi * 16 + lq + rr * 8;
                const float al = 1.f / (1.f + __expf(-g_logit[rg] * INV_SQRT_D));
                const float* urow = umat + (size_t)rg * DMODEL + col0 + wNc;
                const float* hrow = hmat + (size_t)rg * DMODEL + col0 + wNc;
                const size_t base1 = (size_t)rg * KMAX + 2 * DMODEL + col0 + wNc;  // ug
                const size_t base2 = (size_t)rg * KMAX + 3 * DMODEL + col0 + wNc;  // h*ug
#pragma unroll
                for (int n8 = 0; n8 < 4; n8++) {
                    const int cc = n8 * 8 + lr * 2;
                    float2 bb = *(const float2*)(bias + col0 + wNc + cc);
                    float2 u2 = *(const float2*)(urow + cc);
                    float2 h2 = *(const float2*)(hrow + cc);
                    float z0 = acc[mi][n8][rr * 2 + 0] + bb.x;
                    float z1 = acc[mi][n8][rr * 2 + 1] + bb.y;
                    float2 o;
                    o.x = al * u2.x / (1.f + __expf(-z0));
                    o.y = al * u2.y / (1.f + __expf(-z1));
                    split_store2(g_Ahi, g_Alo, base1 + cc, o);
                    split_store2(g_Ahi, g_Alo, base2 + cc,
                                 make_float2(o.x * h2.x, o.y * h2.y));
                }
            }
        }
    } else {
#pragma unroll
        for (int mi = 0; mi < 4; mi++) {
#pragma unroll
            for (int rr = 0; rr < 2; rr++) {
                const int rg = row0 + wMr + mi * 16 + lq + rr * 8;
                float* orow = dst + (size_t)rg * DMODEL + col0 + wNc;
#pragma unroll
                for (int n8 = 0; n8 < 4; n8++) {
                    const int cc = n8 * 8 + lr * 2;
                    float2 bb = *(const float2*)(bias + col0 + wNc + cc);
                    float z0 = acc[mi][n8][rr * 2 + 0] + bb.x;
                    float z1 = acc[mi][n8][rr * 2 + 1] + bb.y;
                    float2 o;
                    o.x = 0.5f * z0 * (1.f + erff(z0 * 0.70710678f));
                    o.y = 0.5f * z1 * (1.f + erff(z1 * 0.70710678f));
                    *(float2*)(orow + cc) = o;
                }
            }
        }
    }
}

extern "C" void kernel_launch(void* const* d_in, const int* in_sizes, int n_in,
                              void* d_out, int out_size) {
    const float* h_t   = (const float*)d_in[0];
    const float* u_t   = (const float*)d_in[1];
    const float* W_a_w = (const float*)d_in[4];
    const float* W_a_b = (const float*)d_in[5];
    const float* W_g_w = (const float*)d_in[6];
    const float* W_g_b = (const float*)d_in[7];
    const float* W_f_w = (const float*)d_in[8];
    const float* W_f_b = (const float*)d_in[9];
    float* out = (float*)d_out;

    cudaFuncSetAttribute(hgemm<0>, cudaFuncAttributeMaxDynamicSharedMemorySize, SMEM_BYTES);
    cudaFuncSetAttribute(hgemm<1>, cudaFuncAttributeMaxDynamicSharedMemorySize, SMEM_BYTES);
    cudaFuncSetAttribute(hgemm<2>, cudaFuncAttributeMaxDynamicSharedMemorySize, SMEM_BYTES);

    __nv_bfloat16 *Wahi, *Walo, *Wghi, *Wglo, *Wfhi, *Wflo;
    cudaGetSymbolAddress((void**)&Wahi, g_Wahi);
    cudaGetSymbolAddress((void**)&Walo, g_Walo);
    cudaGetSymbolAddress((void**)&Wghi, g_Wghi);
    cudaGetSymbolAddress((void**)&Wglo, g_Wglo);
    cudaGetSymbolAddress((void**)&Wfhi, g_Wfhi);
    cudaGetSymbolAddress((void**)&Wflo, g_Wflo);

    dim3 grid(DMODEL / 128, N_TOK / 128);  // (7, 128)
    const int nW = (DMODEL * DMODEL * 6 / 4 + 255) / 256;
    const int nA = (N_TOK * 224 * 2 + 255) / 256;

    // 5 launches; #4 (hgemm<1>) is the ncu-captured launch
    k_convW_all<<<nW, 256>>>(W_a_w, W_g_w, W_f_w);                              // 1
    k_convA_hu<<<nA, 256>>>(h_t, u_t);                                          // 2
    hgemm<0><<<grid, 256, SMEM_BYTES>>>(h_t, u_t, Wahi, Walo, W_a_b, nullptr);  // 3
    hgemm<1><<<grid, 256, SMEM_BYTES>>>(h_t, u_t, Wghi, Wglo, W_g_b, nullptr);  // 4
    hgemm<2><<<grid, 256, SMEM_BYTES>>>(h_t, u_t, Wfhi, Wflo, W_f_b, out);      // 5
}

// round 8
// speedup vs baseline: 1.2474x; 1.0566x over previous
#include <cuda_runtime.h>
#include <cuda_bf16.h>
#include <math.h>
#include <cstdint>

#define N_TOK 16384
#define DMODEL 896
#define KMAX 3584   // [h | alpha*u | ug | h*ug]
#define INV_SQRT_D 0.03340766f   // 1/sqrt(896)

// ---------------- scratch (device globals) ----------------
__device__ float g_logit_part[N_TOK * 8];
__device__ float g_logit[N_TOK];
__device__ __align__(16) __nv_bfloat16 g_Ahi[(size_t)N_TOK * KMAX];
__device__ __align__(16) __nv_bfloat16 g_Alo[(size_t)N_TOK * KMAX];
__device__ __align__(16) __nv_bfloat16 g_Wahi[DMODEL * DMODEL],     g_Walo[DMODEL * DMODEL];
__device__ __align__(16) __nv_bfloat16 g_Wghi[DMODEL * 2 * DMODEL], g_Wglo[DMODEL * 2 * DMODEL];
__device__ __align__(16) __nv_bfloat16 g_Wfhi[DMODEL * 3 * DMODEL], g_Wflo[DMODEL * 3 * DMODEL];

// ---------------- helpers ----------------
static __device__ __forceinline__ uint32_t smem_u32(const void* p) {
    uint32_t a;
    asm("{ .reg .u64 t; cvta.to.shared.u64 t, %1; cvt.u32.u64 %0, t; }" : "=r"(a) : "l"(p));
    return a;
}
static __device__ __forceinline__ void cp16(uint32_t s, const void* g) {
    asm volatile("cp.async.cg.shared.global [%0], [%1], 16;" :: "r"(s), "l"(g));
}
#define CP_COMMIT() asm volatile("cp.async.commit_group;" ::: "memory")
#define CP_WAIT0()  asm volatile("cp.async.wait_group 0;" ::: "memory")

static __device__ __forceinline__ void ldmx4(uint32_t* r, uint32_t addr) {
    asm volatile("ldmatrix.sync.aligned.m8n8.x4.shared.b16 {%0,%1,%2,%3}, [%4];"
        : "=r"(r[0]), "=r"(r[1]), "=r"(r[2]), "=r"(r[3]) : "r"(addr));
}
static __device__ __forceinline__ void mma16816(float* c, const uint32_t* a,
                                                uint32_t b0, uint32_t b1) {
    asm volatile("mma.sync.aligned.m16n8k16.row.col.f32.bf16.bf16.f32 "
        "{%0,%1,%2,%3}, {%4,%5,%6,%7}, {%8,%9}, {%0,%1,%2,%3};"
        : "+f"(c[0]), "+f"(c[1]), "+f"(c[2]), "+f"(c[3])
        : "r"(a[0]), "r"(a[1]), "r"(a[2]), "r"(a[3]), "r"(b0), "r"(b1));
}

static __device__ __forceinline__ void split_store(__nv_bfloat16* hi, __nv_bfloat16* lo,
                                                   size_t idx, float4 v) {
    uint32_t h01, h23, l01, l23;
    asm("cvt.rn.bf16x2.f32 %0, %1, %2;" : "=r"(h01) : "f"(v.y), "f"(v.x));
    asm("cvt.rn.bf16x2.f32 %0, %1, %2;" : "=r"(h23) : "f"(v.w), "f"(v.z));
    float hx = __uint_as_float(h01 << 16), hy = __uint_as_float(h01 & 0xffff0000u);
    float hz = __uint_as_float(h23 << 16), hw = __uint_as_float(h23 & 0xffff0000u);
    asm("cvt.rn.bf16x2.f32 %0, %1, %2;" : "=r"(l01) : "f"(v.y - hy), "f"(v.x - hx));
    asm("cvt.rn.bf16x2.f32 %0, %1, %2;" : "=r"(l23) : "f"(v.w - hw), "f"(v.z - hz));
    *(uint2*)(hi + idx) = make_uint2(h01, h23);
    *(uint2*)(lo + idx) = make_uint2(l01, l23);
}
static __device__ __forceinline__ void split_store2(__nv_bfloat16* hi, __nv_bfloat16* lo,
                                                    size_t idx, float2 v) {
    uint32_t h01, l01;
    asm("cvt.rn.bf16x2.f32 %0, %1, %2;" : "=r"(h01) : "f"(v.y), "f"(v.x));
    float hx = __uint_as_float(h01 << 16);
    float hy = __uint_as_float(h01 & 0xffff0000u);
    asm("cvt.rn.bf16x2.f32 %0, %1, %2;" : "=r"(l01) : "f"(v.y - hy), "f"(v.x - hx));
    *(uint32_t*)(hi + idx) = h01;
    *(uint32_t*)(lo + idx) = l01;
}

// ---------------- fused conversion kernel (W splits + A[h|u] splits) ----------------
#define NA_ITEMS (N_TOK * 224 * 2)
#define NW_ITEMS (DMODEL * (DMODEL + 2 * DMODEL + 3 * DMODEL) / 4)   // 1204224
__global__ void k_conv_all(const float* __restrict__ h, const float* __restrict__ u,
                           const float* __restrict__ wa, const float* __restrict__ wg,
                           const float* __restrict__ wf) {
    int i = blockIdx.x * blockDim.x + threadIdx.x;
    const int half = N_TOK * 224;
    if (i < half) {
        int row = i / 224, c4 = (i % 224) * 4;
        split_store(g_Ahi, g_Alo, (size_t)row * KMAX + c4,
                    *(const float4*)(h + (size_t)row * DMODEL + c4));
    } else if (i < 2 * half) {
        int j = i - half;
        int row = j / 224, c4 = (j % 224) * 4;
        split_store(g_Ahi, g_Alo, (size_t)row * KMAX + DMODEL + c4,
                    *(const float4*)(u + (size_t)row * DMODEL + c4));
    } else {
        int j = i - 2 * half;
        const int n1 = DMODEL * DMODEL / 4;
        const int n2 = DMODEL * 2 * DMODEL / 4;
        const int n3 = DMODEL * 3 * DMODEL / 4;
        if (j < n1) {
            split_store(g_Wahi, g_Walo, (size_t)j * 4, ((const float4*)wa)[j]);
        } else if (j < n1 + n2) {
            int k = j - n1;
            split_store(g_Wghi, g_Wglo, (size_t)k * 4, ((const float4*)wg)[k]);
        } else if (j < n1 + n2 + n3) {
            int k = j - n1 - n2;
            split_store(g_Wfhi, g_Wflo, (size_t)k * 4, ((const float4*)wf)[k]);
        }
    }
}

// one warp per row: reduce logit partials, compute alpha, overwrite A[896:1792] with alpha*u
__global__ void k_alpha(const float* __restrict__ u) {
    const int row = blockIdx.x * 8 + (threadIdx.x >> 5);
    const int l = threadIdx.x & 31;
    float s = (l < 7) ? g_logit_part[(size_t)row * 8 + l] : 0.f;
    s += __shfl_xor_sync(0xffffffffu, s, 1);
    s += __shfl_xor_sync(0xffffffffu, s, 2);
    s += __shfl_xor_sync(0xffffffffu, s, 4);
    s = __shfl_sync(0xffffffffu, s, 0);
    if (l == 0) g_logit[row] = s;
    const float a = 1.f / (1.f + __expf(-s * INV_SQRT_D));
    const float* ur = u + (size_t)row * DMODEL;
    const size_t base = (size_t)row * KMAX + DMODEL;
#pragma unroll
    for (int j = 0; j < 7; j++) {
        const int c4 = (j * 32 + l) * 4;
        float4 v = *(const float4*)(ur + c4);
        v.x *= a; v.y *= a; v.z *= a; v.w *= a;
        split_store(g_Ahi, g_Alo, base + c4, v);
    }
}

// ---------------- bf16x3 HMMA GEMM (256 thr, 2x4 warps, 64x32 warp tile) ----------------
#define ROWB    80
#define TILE_B  (128 * ROWB)         // 10240
#define T_AHI   0
#define T_ALO   TILE_B
#define T_BHI   (2 * TILE_B)
#define T_BLO   (3 * TILE_B)
#define STAGE_STRIDE 65536           // power-of-two stage stride: stage off = (t&1)<<16
#define SMEM_BYTES (STAGE_STRIDE + 4 * TILE_B)   // 106496; 2 CTAs = 208KB <= 228KB

// MODE 0: K=896 (A = u slot). Epi: logit partials
// MODE 1: K=1792 (A=[h|alpha u]). Epi: ug -> A[1792:2688], h*ug -> A[2688:3584]
// MODE 2: K=2688 (A = {[0:896),[1792:3584)}). Epi: dst = gelu_erf(z)
template <int MODE>
__global__ void __launch_bounds__(256, 2) hgemm(
    const float* __restrict__ hmat, const float* __restrict__ umat,
    const __nv_bfloat16* __restrict__ Whi, const __nv_bfloat16* __restrict__ Wlo,
    const float* __restrict__ bias, float* __restrict__ dst)
{
    constexpr int K = (MODE == 0) ? 896 : (MODE == 1 ? 1792 : 2688);
    constexpr int AOFF = (MODE == 0) ? 896 : 0;
    constexpr int NT = K / 32;
    extern __shared__ __align__(16) char smem[];
    const uint32_t sb = smem_u32(smem);

    const int tid = threadIdx.x, wid = tid >> 5, l = tid & 31;
    const int cb = blockIdx.x, rb = blockIdx.y;
    const int row0 = rb * 128, col0 = cb * 128;

    // ---- loader mapping: each thread owns one smem row, 2 of 4 16B chunks ----
    const int lrow = tid >> 1, lc = (tid & 1) * 2;
    // running global pointers (incremented per issued chunk -> no per-iter IMAD chains)
    const __nv_bfloat16* pAh = g_Ahi + (size_t)(row0 + lrow) * KMAX + AOFF + lc * 8;
    const __nv_bfloat16* pAl = g_Alo + (size_t)(row0 + lrow) * KMAX + AOFF + lc * 8;
    const __nv_bfloat16* pBh = Whi + (size_t)(col0 + lrow) * K + lc * 8;
    const __nv_bfloat16* pBl = Wlo + (size_t)(col0 + lrow) * K + lc * 8;
    const uint32_t sl = sb + (uint32_t)(lrow * ROWB + lc * 16);

    int nextk = 0;  // k-elems issued so far (for MODE2 jump detection)
    auto issue = [&]() {
        const uint32_t so = sl + (uint32_t)((nextk >> 5) & 1) * STAGE_STRIDE;
        cp16(so + T_AHI, pAh);      cp16(so + T_AHI + 16, pAh + 8);
        cp16(so + T_ALO, pAl);      cp16(so + T_ALO + 16, pAl + 8);
        cp16(so + T_BHI, pBh);      cp16(so + T_BHI + 16, pBh + 8);
        cp16(so + T_BLO, pBl);      cp16(so + T_BLO + 16, pBl + 8);
        CP_COMMIT();
        nextk += 32;
        int adv = 32;
        if (MODE == 2 && nextk == DMODEL) adv += DMODEL;  // jump over alpha*u slot
        pAh += adv; pAl += adv; pBh += 32; pBl += 32;
    };

    // ---- warp tiling: 2 (M) x 4 (N); warp tile 64x32 ----
    const int wM = wid & 1, wN = wid >> 1;
    const int wMr = wM * 64, wNc = wN * 32;
    const int lq = l >> 2, lr = l & 3;

    float acc[4][4][4];
#pragma unroll
    for (int a = 0; a < 4; a++)
#pragma unroll
        for (int b = 0; b < 4; b++)
#pragma unroll
            for (int c = 0; c < 4; c++) acc[a][b][c] = 0.f;

    // ---- precomputed ldmatrix base addresses (stage offset = (t&1)<<16) ----
    const uint32_t kHalf = (uint32_t)((l >> 4) * 16);
    const uint32_t aHi0 = sb + T_AHI + (uint32_t)((wMr + (l & 15)) * ROWB) + kHalf;
    const uint32_t aLo0 = aHi0 + TILE_B;
    const uint32_t bHi0 = sb + T_BHI + (uint32_t)((wNc + (l & 15)) * ROWB) + kHalf;
    const uint32_t bLo0 = bHi0 + TILE_B;

    issue();
    for (int t = 0; t < NT; t++) {
        CP_WAIT0();
        __syncthreads();
        if (t + 1 < NT) issue();

        const uint32_t stb = (uint32_t)((t & 1) << 16);
#pragma unroll
        for (int s2 = 0; s2 < 2; s2++) {
            const uint32_t off = stb + (uint32_t)(s2 * 32);
            uint32_t bh[2][4], bl[2][4];
#pragma unroll
            for (int nj = 0; nj < 2; nj++) {
                ldmx4(bh[nj], bHi0 + off + (uint32_t)(nj * 16 * ROWB));
                ldmx4(bl[nj], bLo0 + off + (uint32_t)(nj * 16 * ROWB));
            }
#pragma unroll
            for (int mi = 0; mi < 4; mi++) {
                uint32_t af[4];
                ldmx4(af, aHi0 + off + (uint32_t)(mi * 16 * ROWB));
#pragma unroll
                for (int nj = 0; nj < 2; nj++) {
                    mma16816(acc[mi][nj * 2 + 0], af, bh[nj][0], bh[nj][2]);
                    mma16816(acc[mi][nj * 2 + 1], af, bh[nj][1], bh[nj][3]);
                }
#pragma unroll
                for (int nj = 0; nj < 2; nj++) {
                    mma16816(acc[mi][nj * 2 + 0], af, bl[nj][0], bl[nj][2]);
                    mma16816(acc[mi][nj * 2 + 1], af, bl[nj][1], bl[nj][3]);
                }
                ldmx4(af, aLo0 + off + (uint32_t)(mi * 16 * ROWB));
#pragma unroll
                for (int nj = 0; nj < 2; nj++) {
                    mma16816(acc[mi][nj * 2 + 0], af, bh[nj][0], bh[nj][2]);
                    mma16816(acc[mi][nj * 2 + 1], af, bh[nj][1], bh[nj][3]);
                }
            }
        }
        __syncthreads();
    }

    // ---- epilogues ----
    if (MODE == 0) {
        __syncthreads();
        float* red = (float*)smem;  // [128][4]
#pragma unroll
        for (int mi = 0; mi < 4; mi++) {
#pragma unroll
            for (int rr = 0; rr < 2; rr++) {
                const int rloc = wMr + mi * 16 + lq + rr * 8;
                const float* hrow = hmat + (size_t)(row0 + rloc) * DMODEL + col0 + wNc;
                float s = 0.f;
#pragma unroll
                for (int n8 = 0; n8 < 4; n8++) {
                    const int cc = n8 * 8 + lr * 2;
                    float2 h2 = *(const float2*)(hrow + cc);
                    float2 bb = *(const float2*)(bias + col0 + wNc + cc);
                    s += h2.x * (acc[mi][n8][rr * 2 + 0] + bb.x)
                       + h2.y * (acc[mi][n8][rr * 2 + 1] + bb.y);
                }
                s += __shfl_xor_sync(0xffffffffu, s, 1);
                s += __shfl_xor_sync(0xffffffffu, s, 2);
                if (lr == 0) red[rloc * 4 + wN] = s;
            }
        }
        __syncthreads();
        if (tid < 128) {
            float s = red[tid * 4] + red[tid * 4 + 1] + red[tid * 4 + 2] + red[tid * 4 + 3];
            g_logit_part[(size_t)(row0 + tid) * 8 + cb] = s;
        }
    } else if (MODE == 1) {
#pragma unroll
        for (int mi = 0; mi < 4; mi++) {
#pragma unroll
            for (int rr = 0; rr < 2; rr++) {
                const int rg = row0 + wMr + mi * 16 + lq + rr * 8;
                const float al = 1.f / (1.f + __expf(-g_logit[rg] * INV_SQRT_D));
                const float* urow = umat + (size_t)rg * DMODEL + col0 + wNc;
                const float* hrow = hmat + (size_t)rg * DMODEL + col0 + wNc;
                const size_t base1 = (size_t)rg * KMAX + 2 * DMODEL + col0 + wNc;  // ug
                const size_t base2 = (size_t)rg * KMAX + 3 * DMODEL + col0 + wNc;  // h*ug
#pragma unroll
                for (int n8 = 0; n8 < 4; n8++) {
                    const int cc = n8 * 8 + lr * 2;
                    float2 bb = *(const float2*)(bias + col0 + wNc + cc);
                    float2 u2 = *(const float2*)(urow + cc);
                    float2 h2 = *(const float2*)(hrow + cc);
                    float z0 = acc[mi][n8][rr * 2 + 0] + bb.x;
                    float z1 = acc[mi][n8][rr * 2 + 1] + bb.y;
                    float2 o;
                    o.x = al * u2.x / (1.f + __expf(-z0));
                    o.y = al * u2.y / (1.f + __expf(-z1));
                    split_store2(g_Ahi, g_Alo, base1 + cc, o);
                    split_store2(g_Ahi, g_Alo, base2 + cc,
                                 make_float2(o.x * h2.x, o.y * h2.y));
                }
            }
        }
    } else {
#pragma unroll
        for (int mi = 0; mi < 4; mi++) {
#pragma unroll
            for (int rr = 0; rr < 2; rr++) {
                const int rg = row0 + wMr + mi * 16 + lq + rr * 8;
                float* orow = dst + (size_t)rg * DMODEL + col0 + wNc;
#pragma unroll
                for (int n8 = 0; n8 < 4; n8++) {
                    const int cc = n8 * 8 + lr * 2;
                    float2 bb = *(const float2*)(bias + col0 + wNc + cc);
                    float z0 = acc[mi][n8][rr * 2 + 0] + bb.x;
                    float z1 = acc[mi][n8][rr * 2 + 1] + bb.y;
                    float2 o;
                    o.x = 0.5f * z0 * (1.f + erff(z0 * 0.70710678f));
                    o.y = 0.5f * z1 * (1.f + erff(z1 * 0.70710678f));
                    *(float2*)(orow + cc) = o;
                }
            }
        }
    }
}

extern "C" void kernel_launch(void* const* d_in, const int* in_sizes, int n_in,
                              void* d_out, int out_size) {
    const float* h_t   = (const float*)d_in[0];
    const float* u_t   = (const float*)d_in[1];
    const float* W_a_w = (const float*)d_in[4];
    const float* W_a_b = (const float*)d_in[5];
    const float* W_g_w = (const float*)d_in[6];
    const float* W_g_b = (const float*)d_in[7];
    const float* W_f_w = (const float*)d_in[8];
    const float* W_f_b = (const float*)d_in[9];
    float* out = (float*)d_out;

    cudaFuncSetAttribute(hgemm<0>, cudaFuncAttributeMaxDynamicSharedMemorySize, SMEM_BYTES);
    cudaFuncSetAttribute(hgemm<1>, cudaFuncAttributeMaxDynamicSharedMemorySize, SMEM_BYTES);
    cudaFuncSetAttribute(hgemm<2>, cudaFuncAttributeMaxDynamicSharedMemorySize, SMEM_BYTES);

    __nv_bfloat16 *Wahi, *Walo, *Wghi, *Wglo, *Wfhi, *Wflo;
    cudaGetSymbolAddress((void**)&Wahi, g_Wahi);
    cudaGetSymbolAddress((void**)&Walo, g_Walo);
    cudaGetSymbolAddress((void**)&Wghi, g_Wghi);
    cudaGetSymbolAddress((void**)&Wglo, g_Wglo);
    cudaGetSymbolAddress((void**)&Wfhi, g_Wfhi);
    cudaGetSymbolAddress((void**)&Wflo, g_Wflo);

    dim3 grid(DMODEL / 128, N_TOK / 128);  // (7, 128)
    const int nConv = (NA_ITEMS + NW_ITEMS + 255) / 256;

    // 5 launches; #4 (hgemm<1>) is the ncu-captured launch
    k_conv_all<<<nConv, 256>>>(h_t, u_t, W_a_w, W_g_w, W_f_w);                  // 1
    hgemm<0><<<grid, 256, SMEM_BYTES>>>(h_t, u_t, Wahi, Walo, W_a_b, nullptr);  // 2
    k_alpha<<<N_TOK / 8, 256>>>(u_t);                                           // 3
    hgemm<1><<<grid, 256, SMEM_BYTES>>>(h_t, u_t, Wghi, Wglo, W_g_b, nullptr);  // 4
    hgemm<2><<<grid, 256, SMEM_BYTES>>>(h_t, u_t, Wfhi, Wflo, W_f_b, out);      // 5
}